// round 1
// baseline (speedup 1.0000x reference)
#include <cuda_runtime.h>
#include <cuda_bf16.h>
#include <math_constants.h>

#define D 256
#define H 8
#define HD 32
#define S 255
#define S1 256
#define B 4
#define TI 4

// ---------------- device scratch (no allocations allowed) ----------------
__device__ float g_U[B * S * D];      // desc @ eW1[:, :D].T              (no bias)
__device__ float g_V2[B * S * D];     // desc @ eW1[:, D:].T + eb1
__device__ float g_Vmat[B * S1 * D];  // nve @ vW.T + vb
__device__ float g_sq[B * H * S1];    // per-row q-logit scalar (incl. qb-part + ab)
__device__ float g_sk[B * H * S1];    // per-row k-logit scalar (incl. kb-part)
__device__ float g_aq[H * D];
__device__ float g_ak[H * D];
__device__ float g_W2h[H * D];
__device__ float g_bq[H];
__device__ float g_bk[H];
__device__ float g_ce[H];

// ---------------- K1: precompose weight-only vectors ----------------
__global__ void k_prep(const float* __restrict__ qW, const float* __restrict__ qb,
                       const float* __restrict__ kW, const float* __restrict__ kb,
                       const float* __restrict__ eW2, const float* __restrict__ eb2,
                       const float* __restrict__ aW, const float* __restrict__ ab) {
    int t = threadIdx.x;  // 256 threads; t = input channel
    __shared__ float w[3 * HD];
    if (t < 3 * HD) w[t] = aW[t];
    __syncthreads();
#pragma unroll
    for (int h = 0; h < H; h++) {
        float sq = 0.f, sk = 0.f, se = 0.f;
#pragma unroll
        for (int d = 0; d < HD; d++) {
            int row = h * HD + d;
            sq += w[d]          * qW[row * D + t];
            sk += w[HD + d]     * kW[row * D + t];
            se += w[2 * HD + d] * eW2[row * D + t];
        }
        g_aq[h * D + t] = sq;
        g_ak[h * D + t] = sk;
        g_W2h[h * D + t] = se;
    }
    if (t < H) {
        float bq = ab[0], bk = 0.f, ce = 0.f;
#pragma unroll
        for (int d = 0; d < HD; d++) {
            bq += w[d] * qb[t * HD + d];
            bk += w[HD + d] * kb[t * HD + d];
            ce += w[2 * HD + d] * eb2[t * HD + d];
        }
        g_bq[t] = bq; g_bk[t] = bk; g_ce[t] = ce;
    }
}

// ---------------- K2: generic row GEMM  Y[r,o] = sum_in X[r,in]*W[o*stride+off+in] + bias[o]
__global__ void k_rowgemm(const float* __restrict__ X, const float* __restrict__ W,
                          const float* __restrict__ bias, float* __restrict__ Y,
                          int nrows, int wstride, int woff) {
    __shared__ float xs[16][D];
    int r0 = blockIdx.x * 16;
    int t = threadIdx.x;  // 256 threads: output channel
#pragma unroll
    for (int r = 0; r < 16; r++) {
        int rr = r0 + r;
        xs[r][t] = (rr < nrows) ? X[rr * D + t] : 0.f;
    }
    __syncthreads();
    float acc[16];
#pragma unroll
    for (int r = 0; r < 16; r++) acc[r] = 0.f;
    const float4* W4 = (const float4*)(W + t * wstride + woff);
#pragma unroll 4
    for (int i4 = 0; i4 < D / 4; i4++) {
        float4 wv = W4[i4];
#pragma unroll
        for (int r = 0; r < 16; r++) {
            acc[r] += xs[r][i4 * 4 + 0] * wv.x + xs[r][i4 * 4 + 1] * wv.y
                    + xs[r][i4 * 4 + 2] * wv.z + xs[r][i4 * 4 + 3] * wv.w;
        }
    }
    float bv = bias ? bias[t] : 0.f;
#pragma unroll
    for (int r = 0; r < 16; r++) {
        int rr = r0 + r;
        if (rr < nrows) Y[rr * D + t] = acc[r] + bv;
    }
}

// ---------------- K3: per-row attention scalars sq, sk ----------------
__global__ void k_sqsk(const float* __restrict__ X) {
    int task = blockIdx.x * blockDim.x + threadIdx.x;  // 8192 = 1024 rows * 8 heads
    int row = task >> 3, h = task & 7;
    const float* x = X + row * D;
    const float* aq = g_aq + h * D;
    const float* ak = g_ak + h * D;
    float sq = g_bq[h], sk = g_bk[h];
#pragma unroll 8
    for (int in = 0; in < D; in++) {
        float xv = x[in];
        sq += xv * aq[in];
        sk += xv * ak[in];
    }
    int b = row >> 8, i = row & 255;
    g_sq[(b * H + h) * S1 + i] = sq;
    g_sk[(b * H + h) * S1 + i] = sk;
}

// ---------------- K4: fused edge-LN-project + softmax + ctx ----------------
__global__ void __launch_bounds__(256) k_main(const float* __restrict__ ln_g,
                                              const float* __restrict__ ln_b,
                                              float* __restrict__ out) {
    __shared__ float logits[TI][H][S1];  // 32 KB; later reused to hold attn
    __shared__ float usm[TI][D];         // 4 KB
    __shared__ float sks[H][S1];         // 8 KB  (sk + ce folded)
    __shared__ float sqs[TI][H];

    const int t = threadIdx.x, lane = t & 31, w = t >> 5;
    const int b = blockIdx.x / (S1 / TI);
    const int i0 = (blockIdx.x % (S1 / TI)) * TI;
    const bool has0 = (i0 == 0);

    // stage shared state
#pragma unroll
    for (int il = 0; il < TI; il++) {
        int gi = i0 + il;
        usm[il][t] = (gi >= 1) ? g_U[(b * S + gi - 1) * D + t] : 0.f;
    }
    {   // warp w loads head w's sk row (+ce)
        float ce = g_ce[w];
        for (int j = lane; j < S1; j += 32) sks[w][j] = g_sk[(b * H + w) * S1 + j] + ce;
    }
    if (t < TI * H) {
        int il = t / H, h = t % H;
        sqs[il][h] = g_sq[(b * H + h) * S1 + i0 + il];
    }

    // per-lane weight registers
    float gam[8], bet[8], wh[8][8];
#pragma unroll
    for (int k = 0; k < 8; k++) {
        gam[k] = ln_g[lane + 32 * k];
        bet[k] = ln_b[lane + 32 * k];
    }
#pragma unroll
    for (int h = 0; h < 8; h++)
#pragma unroll
        for (int k = 0; k < 8; k++) wh[h][k] = g_W2h[h * D + lane + 32 * k];
    __syncthreads();

    // ---- phase 1: edge logits (warp per j) ----
    for (int j = 1 + w; j < S1; j += 8) {
        const float* v2 = g_V2 + (b * S + j - 1) * D;
        float v2v[8], u0v[8];
#pragma unroll
        for (int k = 0; k < 8; k++) v2v[k] = v2[lane + 32 * k];
        if (has0) {
            const float* uj = g_U + (b * S + j - 1) * D;
#pragma unroll
            for (int k = 0; k < 8; k++) u0v[k] = uj[lane + 32 * k];
        }
#pragma unroll
        for (int il = 0; il < TI; il++) {
            float hv[8];
#pragma unroll
            for (int k = 0; k < 8; k++) {
                float uu = (has0 && il == 0) ? u0v[k] : usm[il][lane + 32 * k];
                hv[k] = uu + v2v[k];
            }
            float s1 = 0.f, s2 = 0.f;
#pragma unroll
            for (int k = 0; k < 8; k++) { s1 += hv[k]; s2 += hv[k] * hv[k]; }
#pragma unroll
            for (int o = 16; o > 0; o >>= 1) {
                s1 += __shfl_xor_sync(0xffffffffu, s1, o);
                s2 += __shfl_xor_sync(0xffffffffu, s2, o);
            }
            float mean = s1 * (1.f / D);
            float var = s2 * (1.f / D) - mean * mean;
            float rstd = rsqrtf(var + 1e-5f);
            float acc[8];
#pragma unroll
            for (int h = 0; h < 8; h++) acc[h] = 0.f;
#pragma unroll
            for (int k = 0; k < 8; k++) {
                float hn = fmaxf(fmaf(gam[k], (hv[k] - mean) * rstd, bet[k]), 0.f);
#pragma unroll
                for (int h = 0; h < 8; h++) acc[h] += hn * wh[h][k];
            }
#pragma unroll
            for (int o = 16; o > 0; o >>= 1)
#pragma unroll
                for (int h = 0; h < 8; h++) acc[h] += __shfl_xor_sync(0xffffffffu, acc[h], o);
            if (lane == 0) {
#pragma unroll
                for (int h = 0; h < 8; h++)
                    logits[il][h][j] = acc[h] + sqs[il][h] + sks[h][j];
            }
        }
    }
    __syncthreads();

    // ---- phase 2: softmax per (il, h), write attn ----
    float* out_attn = out + B * S1 * H * HD;  // attn starts after basis_outputs
    for (int rowid = w; rowid < TI * H; rowid += 8) {
        int il = rowid >> 3, h = rowid & 7;
        float vals[8];
        float m = -CUDART_INF_F;
#pragma unroll
        for (int k = 0; k < 8; k++) {
            int j = lane + 32 * k;
            float lv = (j == 0) ? -CUDART_INF_F : logits[il][h][j];
            vals[k] = lv;
            m = fmaxf(m, lv);
        }
#pragma unroll
        for (int o = 16; o > 0; o >>= 1) m = fmaxf(m, __shfl_xor_sync(0xffffffffu, m, o));
        float s = 0.f;
#pragma unroll
        for (int k = 0; k < 8; k++) {
            int j = lane + 32 * k;
            float e = (j == 0) ? 0.f : __expf(vals[k] - m);
            vals[k] = e;
            s += e;
        }
#pragma unroll
        for (int o = 16; o > 0; o >>= 1) s += __shfl_xor_sync(0xffffffffu, s, o);
        float inv = 1.f / s;
        float* arow = out_attn + ((size_t)(b * H + h) * S1 + (i0 + il)) * S1;
#pragma unroll
        for (int k = 0; k < 8; k++) {
            float a = vals[k] * inv;
            arow[lane + 32 * k] = a;
            logits[il][h][lane + 32 * k] = a;  // keep for ctx phase
        }
    }
    __syncthreads();

    // ---- phase 3: ctx = attn @ v  (warp = head) ----
    {
        const int h = w;
        const float* vb = g_Vmat + ((size_t)b * S1) * D + h * HD + lane;
        float a0 = 0.f, a1 = 0.f, a2 = 0.f, a3 = 0.f;
        for (int j = 1; j < S1; j++) {
            float vv = vb[(size_t)j * D];
            a0 = fmaf(logits[0][h][j], vv, a0);
            a1 = fmaf(logits[1][h][j], vv, a1);
            a2 = fmaf(logits[2][h][j], vv, a2);
            a3 = fmaf(logits[3][h][j], vv, a3);
        }
        out[(((size_t)b * S1 + i0 + 0) * H + h) * HD + lane] = a0;
        out[(((size_t)b * S1 + i0 + 1) * H + h) * HD + lane] = a1;
        out[(((size_t)b * S1 + i0 + 2) * H + h) * HD + lane] = a2;
        out[(((size_t)b * S1 + i0 + 3) * H + h) * HD + lane] = a3;
    }
}

// ---------------- launch ----------------
extern "C" void kernel_launch(void* const* d_in, const int* in_sizes, int n_in,
                              void* d_out, int out_size) {
    const float* desc = (const float*)d_in[0];
    const float* nve  = (const float*)d_in[1];
    const float* qW = (const float*)d_in[2];
    const float* qb = (const float*)d_in[3];
    const float* kW = (const float*)d_in[4];
    const float* kb = (const float*)d_in[5];
    const float* vW = (const float*)d_in[6];
    const float* vb = (const float*)d_in[7];
    const float* eW1 = (const float*)d_in[8];
    const float* eb1 = (const float*)d_in[9];
    const float* ln_g = (const float*)d_in[10];
    const float* ln_b = (const float*)d_in[11];
    const float* eW2 = (const float*)d_in[12];
    const float* eb2 = (const float*)d_in[13];
    const float* aW = (const float*)d_in[14];
    const float* ab = (const float*)d_in[15];
    float* out = (float*)d_out;

    float *pU, *pV2, *pVm;
    cudaGetSymbolAddress((void**)&pU, g_U);
    cudaGetSymbolAddress((void**)&pV2, g_V2);
    cudaGetSymbolAddress((void**)&pVm, g_Vmat);

    k_prep<<<1, 256>>>(qW, qb, kW, kb, eW2, eb2, aW, ab);
    k_rowgemm<<<(B * S1 + 15) / 16, 256>>>(nve, vW, vb, pVm, B * S1, D, 0);
    k_rowgemm<<<(B * S + 15) / 16, 256>>>(desc, eW1, nullptr, pU, B * S, 2 * D, 0);
    k_rowgemm<<<(B * S + 15) / 16, 256>>>(desc, eW1, eb1, pV2, B * S, 2 * D, D);
    k_sqsk<<<(B * S1 * H) / 256, 256>>>(nve);
    k_main<<<B * S1 / TI, 256>>>(ln_g, ln_b, out);
}

// round 2
// speedup vs baseline: 1.6085x; 1.6085x over previous
#include <cuda_runtime.h>
#include <cuda_bf16.h>
#include <math_constants.h>

#define D 256
#define H 8
#define HD 32
#define S 255
#define S1 256
#define B 4
#define TI 4

typedef unsigned long long u64;

// ---------------- packed f32x2 helpers ----------------
__device__ __forceinline__ u64 pk2(float lo, float hi) {
    u64 r; asm("mov.b64 %0,{%1,%2};" : "=l"(r) : "f"(lo), "f"(hi)); return r;
}
__device__ __forceinline__ void upk2(u64 v, float& lo, float& hi) {
    asm("mov.b64 {%0,%1},%2;" : "=f"(lo), "=f"(hi) : "l"(v));
}
__device__ __forceinline__ u64 fma2_(u64 a, u64 b, u64 c) {
    u64 d; asm("fma.rn.f32x2 %0,%1,%2,%3;" : "=l"(d) : "l"(a), "l"(b), "l"(c)); return d;
}
__device__ __forceinline__ u64 add2_(u64 a, u64 b) {
    u64 d; asm("add.rn.f32x2 %0,%1,%2;" : "=l"(d) : "l"(a), "l"(b)); return d;
}

// ---------------- device scratch ----------------
__device__ float g_U[B * S * D];        // desc @ eW1[:, :D].T (row-major, for i-side staging)
__device__ u64   g_UT[B * 128 * S1];    // transposed, channel-pair packed: [(b*128+cp)*S1 + j]
__device__ u64   g_V2T[B * 128 * S1];   // (desc @ eW1[:, D:].T + eb1) transposed+packed
__device__ float g_Vmat[B * S1 * D];    // nve @ vW.T + vb
__device__ float g_sU[B * S];           // row sums of U
__device__ float g_sU2[B * S];          // row sumsq of U
__device__ float g_sV[B * S];           // row sums of V2
__device__ float g_sV2[B * S];          // row sumsq of V2
__device__ float g_sq[B * H * S1];
__device__ float g_sk[B * H * S1];
__device__ float g_aq[H * D];
__device__ float g_ak[H * D];
__device__ float g_W2h[H * D];          // pre-scaled by 0.5 (relu trick)
__device__ float g_bq[H];
__device__ float g_bk[H];
__device__ float g_ce[H];

// ---------------- K1: precompose weight-only vectors ----------------
__global__ void k_prep(const float* __restrict__ qW, const float* __restrict__ qb,
                       const float* __restrict__ kW, const float* __restrict__ kb,
                       const float* __restrict__ eW2, const float* __restrict__ eb2,
                       const float* __restrict__ aW, const float* __restrict__ ab) {
    int t = threadIdx.x;  // input channel
    __shared__ float w[3 * HD];
    if (t < 3 * HD) w[t] = aW[t];
    __syncthreads();
#pragma unroll
    for (int h = 0; h < H; h++) {
        float sq = 0.f, sk = 0.f, se = 0.f;
#pragma unroll
        for (int d = 0; d < HD; d++) {
            int row = h * HD + d;
            sq += w[d]          * qW[row * D + t];
            sk += w[HD + d]     * kW[row * D + t];
            se += w[2 * HD + d] * eW2[row * D + t];
        }
        g_aq[h * D + t] = sq;
        g_ak[h * D + t] = sk;
        g_W2h[h * D + t] = 0.5f * se;   // fold relu half
    }
    if (t < H) {
        float bq = ab[0], bk = 0.f, ce = 0.f;
#pragma unroll
        for (int d = 0; d < HD; d++) {
            bq += w[d] * qb[t * HD + d];
            bk += w[HD + d] * kb[t * HD + d];
            ce += w[2 * HD + d] * eb2[t * HD + d];
        }
        g_bq[t] = bq; g_bk[t] = bk; g_ce[t] = ce;
    }
}

// ---------------- K2: fused GEMMs + transposes + row stats + sq/sk ----------------
// blocks [0,64): Vmat; [64,128): U (+UT, sums); [128,192): V2T (+sums); [192,224): sqsk
__global__ void __launch_bounds__(256) k_big(const float* __restrict__ desc,
                                             const float* __restrict__ nve,
                                             const float* __restrict__ vW,
                                             const float* __restrict__ vb,
                                             const float* __restrict__ eW1,
                                             const float* __restrict__ eb1) {
    __shared__ u64 xsp[D][8];        // [channel][rowpair] = {X[2q][c], X[2q+1][c]}
    __shared__ float red[16][8][2];
    int blk = blockIdx.x;
    int t = threadIdx.x;

    if (blk >= 192) {  // ---- sqsk job ----
        int task = (blk - 192) * 256 + t;
        int row = task >> 3, h = task & 7;
        const float* x = nve + row * D;
        const float* aq = g_aq + h * D;
        const float* ak = g_ak + h * D;
        float sq = g_bq[h], sk = g_bk[h];
#pragma unroll 8
        for (int in = 0; in < D; in++) {
            float xv = x[in];
            sq += xv * aq[in];
            sk += xv * ak[in];
        }
        int b = row >> 8, i = row & 255;
        g_sq[(b * H + h) * S1 + i] = sq;
        g_sk[(b * H + h) * S1 + i] = sk;
        return;
    }

    int job = blk >> 6;              // 0: Vmat, 1: U, 2: V2
    int r0 = (blk & 63) * 16;
    const float* X; const float* W; const float* bias;
    int nrows, wstride, woff;
    if (job == 0) { X = nve;  W = vW;  bias = vb;   nrows = B * S1; wstride = D;     woff = 0; }
    else if (job == 1) { X = desc; W = eW1; bias = nullptr; nrows = B * S; wstride = 2 * D; woff = 0; }
    else { X = desc; W = eW1; bias = eb1;  nrows = B * S; wstride = 2 * D; woff = D; }

    // stage X rows (row-pair packed)
#pragma unroll
    for (int r = 0; r < 16; r++) {
        int rr = r0 + r;
        float xv = (rr < nrows) ? X[rr * D + t] : 0.f;
        ((float*)&xsp[t][r >> 1])[r & 1] = xv;
    }
    __syncthreads();

    u64 acc[8];
#pragma unroll
    for (int q = 0; q < 8; q++) acc[q] = 0ull;
    const float4* W4 = (const float4*)(W + t * wstride + woff);
#pragma unroll 2
    for (int c4 = 0; c4 < D / 4; c4++) {
        float4 wv = W4[c4];
        float ws[4] = {wv.x, wv.y, wv.z, wv.w};
#pragma unroll
        for (int cc = 0; cc < 4; cc++) {
            int c = c4 * 4 + cc;
            u64 wp = pk2(ws[cc], ws[cc]);
#pragma unroll
            for (int q = 0; q < 8; q++) acc[q] = fma2_(xsp[c][q], wp, acc[q]);
        }
    }
    float bv = bias ? bias[t] : 0.f;
    float vals[16];
#pragma unroll
    for (int q = 0; q < 8; q++) {
        float lo, hi; upk2(acc[q], lo, hi);
        vals[2 * q] = lo + bv; vals[2 * q + 1] = hi + bv;
    }

    if (job == 0) {
#pragma unroll
        for (int r = 0; r < 16; r++) {
            int rr = r0 + r;
            if (rr < nrows) g_Vmat[rr * D + t] = vals[r];
        }
        return;
    }

    // transposed (and for job 1, row-major) stores
#pragma unroll
    for (int r = 0; r < 16; r++) {
        int rr = r0 + r;
        if (rr < nrows) {
            int bb = rr / S, jm = rr % S, j = jm + 1;
            size_t tidx = ((size_t)(bb * 128 + (t >> 1)) * S1 + j);
            if (job == 1) {
                g_U[rr * D + t] = vals[r];
                ((float*)&g_UT[tidx])[t & 1] = vals[r];
            } else {
                ((float*)&g_V2T[tidx])[t & 1] = vals[r];
            }
        }
    }

    // row sums / sumsq (block reduce over 256 output channels)
    int lane = t & 31, w = t >> 5;
#pragma unroll
    for (int r = 0; r < 16; r++) {
        float s = vals[r], s2 = vals[r] * vals[r];
#pragma unroll
        for (int o = 16; o > 0; o >>= 1) {
            s += __shfl_xor_sync(0xffffffffu, s, o);
            s2 += __shfl_xor_sync(0xffffffffu, s2, o);
        }
        if (lane == 0) { red[r][w][0] = s; red[r][w][1] = s2; }
    }
    __syncthreads();
    if (t < 16) {
        int rr = r0 + t;
        if (rr < nrows) {
            float s = 0.f, s2 = 0.f;
#pragma unroll
            for (int ww = 0; ww < 8; ww++) { s += red[t][ww][0]; s2 += red[t][ww][1]; }
            if (job == 1) { g_sU[rr] = s; g_sU2[rr] = s2; }
            else { g_sV[rr] = s; g_sV2[rr] = s2; }
        }
    }
}

// ---------------- K3 main: edge logits (thread-per-j) + softmax + ctx ----------------
template <bool HAS0>
__device__ __forceinline__ void edge_cols(int b, int i0, int j,
                                          u64 (&usm2)[128][4], u64 (&gbu)[128][2],
                                          u64 (&whu)[128][8], float (&logits)[TI][H][S1],
                                          float (&sqs)[TI][H], float (&ceh)[H]) {
    const u64* v2p = g_V2T + (size_t)b * 128 * S1 + j;
    const u64* utp = g_UT + (size_t)b * 128 * S1 + j;

    // ---- pass 1: cross dots for variance ----
    u64 d2[4] = {0ull, 0ull, 0ull, 0ull};
#pragma unroll 4
    for (int cp = 0; cp < 128; cp++) {
        u64 v2 = v2p[(size_t)cp << 8];
        u64 u0 = HAS0 ? utp[(size_t)cp << 8] : usm2[cp][0];
        d2[0] = fma2_(u0, v2, d2[0]);
        d2[1] = fma2_(usm2[cp][1], v2, d2[1]);
        d2[2] = fma2_(usm2[cp][2], v2, d2[2]);
        d2[3] = fma2_(usm2[cp][3], v2, d2[3]);
    }

    // ---- stats per il ----
    float sv = g_sV[b * S + j - 1], sv2 = g_sV2[b * S + j - 1];
    u64 r2[4], m2[4];
#pragma unroll
    for (int il = 0; il < 4; il++) {
        int gi = i0 + il;
        float su, su2;
        if (HAS0 && il == 0) { su = g_sU[b * S + j - 1]; su2 = g_sU2[b * S + j - 1]; }
        else { su = g_sU[b * S + gi - 1]; su2 = g_sU2[b * S + gi - 1]; }
        float dlo, dhi; upk2(d2[il], dlo, dhi);
        float dot = dlo + dhi;
        float mean = (su + sv) * (1.f / D);
        float msum = su2 + sv2 + 2.f * dot;
        float var = msum * (1.f / D) - mean * mean;
        float rstd = rsqrtf(var + 1e-5f);
        r2[il] = pk2(rstd, rstd);
        float nm = -mean * rstd;
        m2[il] = pk2(nm, nm);
    }

    float skv[H];
#pragma unroll
    for (int h = 0; h < H; h++) skv[h] = g_sk[(b * H + h) * S1 + j] + ceh[h];

    const u64 ABSM = 0x7FFFFFFF7FFFFFFFull;
    // ---- pass 2: normalize + relu + head projection, 2 rows at a time ----
#pragma unroll
    for (int p = 0; p < 2; p++) {
        u64 acc[2][8];
#pragma unroll
        for (int k = 0; k < 2; k++)
#pragma unroll
            for (int h = 0; h < 8; h++) acc[k][h] = 0ull;
#pragma unroll 2
        for (int cp = 0; cp < 128; cp++) {
            u64 v2 = v2p[(size_t)cp << 8];
            u64 ua = (HAS0 && p == 0) ? utp[(size_t)cp << 8] : usm2[cp][2 * p];
            u64 ub = usm2[cp][2 * p + 1];
            u64 g2 = gbu[cp][0], b2 = gbu[cp][1];
            u64 wv[8];
#pragma unroll
            for (int h = 0; h < 8; h++) wv[h] = whu[cp][h];
#pragma unroll
            for (int k = 0; k < 2; k++) {
                u64 hv = add2_(k == 0 ? ua : ub, v2);
                u64 z = fma2_(hv, r2[2 * p + k], m2[2 * p + k]);
                u64 hn = fma2_(g2, z, b2);
                u64 pr = add2_(hn, hn & ABSM);   // 2*relu(hn); 0.5 folded into wh
#pragma unroll
                for (int h = 0; h < 8; h++) acc[k][h] = fma2_(pr, wv[h], acc[k][h]);
            }
        }
#pragma unroll
        for (int k = 0; k < 2; k++) {
            int il = 2 * p + k;
#pragma unroll
            for (int h = 0; h < 8; h++) {
                float lo, hi; upk2(acc[k][h], lo, hi);
                logits[il][h][j] = lo + hi + sqs[il][h] + skv[h];
            }
        }
    }
}

__global__ void __launch_bounds__(256, 2) k_main(const float* __restrict__ ln_g,
                                                 const float* __restrict__ ln_b,
                                                 float* __restrict__ out) {
    __shared__ u64 usm2[128][4];       // 4 KB  {U[il][2cp], U[il][2cp+1]}
    __shared__ u64 gbu[128][2];        // 2 KB  gamma/beta pairs
    __shared__ u64 whu[128][8];        // 8 KB  head-weight pairs (pre-halved)
    __shared__ float logits[TI][H][S1];// 32 KB (reused as attn)
    __shared__ float sqs[TI][H];
    __shared__ float ceh[H];

    const int t = threadIdx.x, lane = t & 31, w = t >> 5;
    const int b = blockIdx.x / (S1 / TI);
    const int i0 = (blockIdx.x % (S1 / TI)) * TI;
    const bool has0 = (i0 == 0);

    // ---- staging ----
#pragma unroll
    for (int il = 0; il < TI; il++) {
        int gi = i0 + il;
        float uv = (gi >= 1) ? g_U[(b * S + gi - 1) * D + t] : 0.f;
        ((float*)&usm2[t >> 1][il])[t & 1] = uv;
    }
    if (t < 128) {
        gbu[t][0] = pk2(ln_g[2 * t], ln_g[2 * t + 1]);
        gbu[t][1] = pk2(ln_b[2 * t], ln_b[2 * t + 1]);
    }
#pragma unroll
    for (int q = 0; q < 4; q++) {
        int id = t + 256 * q;
        int cp = id & 127, h = id >> 7;
        whu[cp][h] = pk2(g_W2h[h * D + 2 * cp], g_W2h[h * D + 2 * cp + 1]);
    }
    if (t < TI * H) {
        int il = t >> 3, h = t & 7;
        sqs[il][h] = g_sq[(b * H + h) * S1 + i0 + il];
    }
    if (t < H) ceh[t] = g_ce[t];
    __syncthreads();

    // ---- phase 1: per-column edge logits ----
    if (t >= 1) {
        if (has0) edge_cols<true>(b, i0, t, usm2, gbu, whu, logits, sqs, ceh);
        else      edge_cols<false>(b, i0, t, usm2, gbu, whu, logits, sqs, ceh);
    }
    __syncthreads();

    // ---- phase 2: softmax per (il, h) ----
    float* out_attn = out + B * S1 * H * HD;
    for (int rowid = w; rowid < TI * H; rowid += 8) {
        int il = rowid >> 3, h = rowid & 7;
        float vals[8];
        float m = -CUDART_INF_F;
#pragma unroll
        for (int k = 0; k < 8; k++) {
            int j = lane + 32 * k;
            float lv = (j == 0) ? -CUDART_INF_F : logits[il][h][j];
            vals[k] = lv;
            m = fmaxf(m, lv);
        }
#pragma unroll
        for (int o = 16; o > 0; o >>= 1) m = fmaxf(m, __shfl_xor_sync(0xffffffffu, m, o));
        float s = 0.f;
#pragma unroll
        for (int k = 0; k < 8; k++) {
            int j = lane + 32 * k;
            float e = (j == 0) ? 0.f : __expf(vals[k] - m);
            vals[k] = e;
            s += e;
        }
#pragma unroll
        for (int o = 16; o > 0; o >>= 1) s += __shfl_xor_sync(0xffffffffu, s, o);
        float inv = 1.f / s;
        float* arow = out_attn + ((size_t)(b * H + h) * S1 + (i0 + il)) * S1;
#pragma unroll
        for (int k = 0; k < 8; k++) {
            float a = vals[k] * inv;
            arow[lane + 32 * k] = a;
            logits[il][h][lane + 32 * k] = a;
        }
    }
    __syncthreads();

    // ---- phase 3: ctx = attn @ v (warp = head) ----
    {
        const int h = w;
        const float* vb = g_Vmat + ((size_t)b * S1) * D + h * HD + lane;
        float a0 = 0.f, a1 = 0.f, a2 = 0.f, a3 = 0.f;
#pragma unroll 4
        for (int j = 1; j < S1; j++) {
            float vv = vb[(size_t)j * D];
            a0 = fmaf(logits[0][h][j], vv, a0);
            a1 = fmaf(logits[1][h][j], vv, a1);
            a2 = fmaf(logits[2][h][j], vv, a2);
            a3 = fmaf(logits[3][h][j], vv, a3);
        }
        out[(((size_t)b * S1 + i0 + 0) * H + h) * HD + lane] = a0;
        out[(((size_t)b * S1 + i0 + 1) * H + h) * HD + lane] = a1;
        out[(((size_t)b * S1 + i0 + 2) * H + h) * HD + lane] = a2;
        out[(((size_t)b * S1 + i0 + 3) * H + h) * HD + lane] = a3;
    }
}

// ---------------- launch ----------------
extern "C" void kernel_launch(void* const* d_in, const int* in_sizes, int n_in,
                              void* d_out, int out_size) {
    const float* desc = (const float*)d_in[0];
    const float* nve  = (const float*)d_in[1];
    const float* qW = (const float*)d_in[2];
    const float* qb = (const float*)d_in[3];
    const float* kW = (const float*)d_in[4];
    const float* kb = (const float*)d_in[5];
    const float* vW = (const float*)d_in[6];
    const float* vb = (const float*)d_in[7];
    const float* eW1 = (const float*)d_in[8];
    const float* eb1 = (const float*)d_in[9];
    const float* ln_g = (const float*)d_in[10];
    const float* ln_b = (const float*)d_in[11];
    const float* eW2 = (const float*)d_in[12];
    const float* eb2 = (const float*)d_in[13];
    const float* aW = (const float*)d_in[14];
    const float* ab = (const float*)d_in[15];
    float* out = (float*)d_out;

    k_prep<<<1, 256>>>(qW, qb, kW, kb, eW2, eb2, aW, ab);
    k_big<<<224, 256>>>(desc, nve, vW, vb, eW1, eb1);
    k_main<<<B * S1 / TI, 256>>>(ln_g, ln_b, out);
}

// round 3
// speedup vs baseline: 2.0293x; 1.2616x over previous
#include <cuda_runtime.h>
#include <cuda_bf16.h>
#include <math_constants.h>

#define D 256
#define H 8
#define HD 32
#define S 255
#define S1 256
#define B 4
#define TI 4

typedef unsigned long long u64;

// ---------------- packed f32x2 helpers ----------------
__device__ __forceinline__ u64 pk2(float lo, float hi) {
    u64 r; asm("mov.b64 %0,{%1,%2};" : "=l"(r) : "f"(lo), "f"(hi)); return r;
}
__device__ __forceinline__ void upk2(u64 v, float& lo, float& hi) {
    asm("mov.b64 {%0,%1},%2;" : "=f"(lo), "=f"(hi) : "l"(v));
}
__device__ __forceinline__ u64 fma2_(u64 a, u64 b, u64 c) {
    u64 d; asm("fma.rn.f32x2 %0,%1,%2,%3;" : "=l"(d) : "l"(a), "l"(b), "l"(c)); return d;
}
__device__ __forceinline__ u64 add2_(u64 a, u64 b) {
    u64 d; asm("add.rn.f32x2 %0,%1,%2;" : "=l"(d) : "l"(a), "l"(b)); return d;
}

// ---------------- device scratch ----------------
__device__ float g_U[B * S * D];        // desc @ eW1[:, :D].T (row-major, for i-side staging)
__device__ u64   g_UT[B * 128 * S1];    // transposed, channel-pair packed: [(b*128+cp)*S1 + j]
__device__ u64   g_V2T[B * 128 * S1];   // (desc @ eW1[:, D:].T + eb1) transposed+packed
__device__ float g_Vmat[B * S1 * D];    // nve @ vW.T + vb
__device__ float g_sU[B * S];           // row sums of U
__device__ float g_sU2[B * S];          // row sumsq of U
__device__ float g_sV[B * S];           // row sums of V2
__device__ float g_sV2[B * S];          // row sumsq of V2
__device__ float g_sq[B * H * S1];
__device__ float g_sk[B * H * S1];
__device__ float g_aq[H * D];
__device__ float g_ak[H * D];
__device__ float g_W2h[H * D];          // pre-scaled by 0.5 (relu trick)
__device__ float g_bq[H];
__device__ float g_bk[H];
__device__ float g_ce[H];

// ---------------- K1: precompose weight-only vectors (parallel) ----------------
// 6144 matrix dots (3 mats x 8 heads x 256 channels, length 32) + 24 bias dots.
__global__ void __launch_bounds__(256) k_prep(
        const float* __restrict__ qW, const float* __restrict__ qb,
        const float* __restrict__ kW, const float* __restrict__ kb,
        const float* __restrict__ eW2, const float* __restrict__ eb2,
        const float* __restrict__ aW, const float* __restrict__ ab) {
    int id = blockIdx.x * 256 + threadIdx.x;
    if (id < 3 * H * D) {
        int m = id >> 11;            // matrix: 0=q, 1=k, 2=e2
        int rem = id & 2047;
        int h = rem >> 8, c = rem & 255;
        const float* W = (m == 0) ? qW : (m == 1) ? kW : eW2;
        const float* w = aW + m * HD;
        float s = 0.f;
#pragma unroll
        for (int d = 0; d < HD; d++)
            s = fmaf(__ldg(&w[d]), W[(h * HD + d) * D + c], s);
        if (m == 0) g_aq[h * D + c] = s;
        else if (m == 1) g_ak[h * D + c] = s;
        else g_W2h[h * D + c] = 0.5f * s;   // fold relu half
    } else if (id < 3 * H * D + 3 * H) {
        int r = id - 3 * H * D;
        int m = r >> 3, h = r & 7;
        const float* bb = (m == 0) ? qb : (m == 1) ? kb : eb2;
        const float* w = aW + m * HD;
        float s = (m == 0) ? ab[0] : 0.f;
#pragma unroll
        for (int d = 0; d < HD; d++)
            s = fmaf(w[d], bb[h * HD + d], s);
        if (m == 0) g_bq[h] = s;
        else if (m == 1) g_bk[h] = s;
        else g_ce[h] = s;
    }
}

// ---------------- K2: fused GEMMs + transposes + row stats + sq/sk ----------------
// blocks [0,64): Vmat; [64,128): U (+UT, sums); [128,192): V2T (+sums); [192,224): sqsk
__global__ void __launch_bounds__(256) k_big(const float* __restrict__ desc,
                                             const float* __restrict__ nve,
                                             const float* __restrict__ vW,
                                             const float* __restrict__ vb,
                                             const float* __restrict__ eW1,
                                             const float* __restrict__ eb1) {
    __shared__ u64 xsp[D][8];        // [channel][rowpair] = {X[2q][c], X[2q+1][c]}
    __shared__ float red[16][8][2];
    int blk = blockIdx.x;
    int t = threadIdx.x;

    if (blk >= 192) {  // ---- sqsk job ----
        int task = (blk - 192) * 256 + t;
        int row = task >> 3, h = task & 7;
        const float* x = nve + row * D;
        const float* aq = g_aq + h * D;
        const float* ak = g_ak + h * D;
        float sq = g_bq[h], sk = g_bk[h];
#pragma unroll 8
        for (int in = 0; in < D; in++) {
            float xv = x[in];
            sq += xv * aq[in];
            sk += xv * ak[in];
        }
        int b = row >> 8, i = row & 255;
        g_sq[(b * H + h) * S1 + i] = sq;
        g_sk[(b * H + h) * S1 + i] = sk;
        return;
    }

    int job = blk >> 6;              // 0: Vmat, 1: U, 2: V2
    int r0 = (blk & 63) * 16;
    const float* X; const float* W; const float* bias;
    int nrows, wstride, woff;
    if (job == 0) { X = nve;  W = vW;  bias = vb;   nrows = B * S1; wstride = D;     woff = 0; }
    else if (job == 1) { X = desc; W = eW1; bias = nullptr; nrows = B * S; wstride = 2 * D; woff = 0; }
    else { X = desc; W = eW1; bias = eb1;  nrows = B * S; wstride = 2 * D; woff = D; }

    // stage X rows (row-pair packed)
#pragma unroll
    for (int r = 0; r < 16; r++) {
        int rr = r0 + r;
        float xv = (rr < nrows) ? X[rr * D + t] : 0.f;
        ((float*)&xsp[t][r >> 1])[r & 1] = xv;
    }
    __syncthreads();

    u64 acc[8];
#pragma unroll
    for (int q = 0; q < 8; q++) acc[q] = 0ull;
    const float4* W4 = (const float4*)(W + t * wstride + woff);
#pragma unroll 2
    for (int c4 = 0; c4 < D / 4; c4++) {
        float4 wv = W4[c4];
        float ws[4] = {wv.x, wv.y, wv.z, wv.w};
#pragma unroll
        for (int cc = 0; cc < 4; cc++) {
            int c = c4 * 4 + cc;
            u64 wp = pk2(ws[cc], ws[cc]);
#pragma unroll
            for (int q = 0; q < 8; q++) acc[q] = fma2_(xsp[c][q], wp, acc[q]);
        }
    }
    float bv = bias ? bias[t] : 0.f;
    float vals[16];
#pragma unroll
    for (int q = 0; q < 8; q++) {
        float lo, hi; upk2(acc[q], lo, hi);
        vals[2 * q] = lo + bv; vals[2 * q + 1] = hi + bv;
    }

    if (job == 0) {
#pragma unroll
        for (int r = 0; r < 16; r++) {
            int rr = r0 + r;
            if (rr < nrows) g_Vmat[rr * D + t] = vals[r];
        }
        return;
    }

    // transposed (and for job 1, row-major) stores
#pragma unroll
    for (int r = 0; r < 16; r++) {
        int rr = r0 + r;
        if (rr < nrows) {
            int bb = rr / S, jm = rr % S, j = jm + 1;
            size_t tidx = ((size_t)(bb * 128 + (t >> 1)) * S1 + j);
            if (job == 1) {
                g_U[rr * D + t] = vals[r];
                ((float*)&g_UT[tidx])[t & 1] = vals[r];
            } else {
                ((float*)&g_V2T[tidx])[t & 1] = vals[r];
            }
        }
    }

    // row sums / sumsq (block reduce over 256 output channels)
    int lane = t & 31, w = t >> 5;
#pragma unroll
    for (int r = 0; r < 16; r++) {
        float s = vals[r], s2 = vals[r] * vals[r];
#pragma unroll
        for (int o = 16; o > 0; o >>= 1) {
            s += __shfl_xor_sync(0xffffffffu, s, o);
            s2 += __shfl_xor_sync(0xffffffffu, s2, o);
        }
        if (lane == 0) { red[r][w][0] = s; red[r][w][1] = s2; }
    }
    __syncthreads();
    if (t < 16) {
        int rr = r0 + t;
        if (rr < nrows) {
            float s = 0.f, s2 = 0.f;
#pragma unroll
            for (int ww = 0; ww < 8; ww++) { s += red[t][ww][0]; s2 += red[t][ww][1]; }
            if (job == 1) { g_sU[rr] = s; g_sU2[rr] = s2; }
            else { g_sV[rr] = s; g_sV2[rr] = s2; }
        }
    }
}

// ---------------- K3 main: edge logits (thread-per-j) + softmax + ctx ----------------
template <bool HAS0>
__device__ __forceinline__ void edge_cols(int b, int i0, int j,
                                          u64 (&usm2)[128][4], u64 (&gbu)[128][2],
                                          u64 (&whu)[128][8], float (&logits)[TI][H][S1],
                                          float (&sqs)[TI][H], float (&ceh)[H]) {
    const u64* v2p = g_V2T + (size_t)b * 128 * S1 + j;
    const u64* utp = g_UT + (size_t)b * 128 * S1 + j;

    // ---- pass 1: cross dots for variance ----
    u64 d2[4] = {0ull, 0ull, 0ull, 0ull};
#pragma unroll 4
    for (int cp = 0; cp < 128; cp++) {
        u64 v2 = v2p[(size_t)cp << 8];
        u64 u0 = HAS0 ? utp[(size_t)cp << 8] : usm2[cp][0];
        d2[0] = fma2_(u0, v2, d2[0]);
        d2[1] = fma2_(usm2[cp][1], v2, d2[1]);
        d2[2] = fma2_(usm2[cp][2], v2, d2[2]);
        d2[3] = fma2_(usm2[cp][3], v2, d2[3]);
    }

    // ---- stats per il ----
    float sv = g_sV[b * S + j - 1], sv2 = g_sV2[b * S + j - 1];
    u64 r2[4], m2[4];
#pragma unroll
    for (int il = 0; il < 4; il++) {
        int gi = i0 + il;
        float su, su2;
        if (HAS0 && il == 0) { su = g_sU[b * S + j - 1]; su2 = g_sU2[b * S + j - 1]; }
        else { su = g_sU[b * S + gi - 1]; su2 = g_sU2[b * S + gi - 1]; }
        float dlo, dhi; upk2(d2[il], dlo, dhi);
        float dot = dlo + dhi;
        float mean = (su + sv) * (1.f / D);
        float msum = su2 + sv2 + 2.f * dot;
        float var = msum * (1.f / D) - mean * mean;
        float rstd = rsqrtf(var + 1e-5f);
        r2[il] = pk2(rstd, rstd);
        float nm = -mean * rstd;
        m2[il] = pk2(nm, nm);
    }

    float skv[H];
#pragma unroll
    for (int h = 0; h < H; h++) skv[h] = g_sk[(b * H + h) * S1 + j] + ceh[h];

    const u64 ABSM = 0x7FFFFFFF7FFFFFFFull;
    // ---- pass 2: normalize + relu + head projection, 2 rows at a time ----
#pragma unroll
    for (int p = 0; p < 2; p++) {
        u64 acc[2][8];
#pragma unroll
        for (int k = 0; k < 2; k++)
#pragma unroll
            for (int h = 0; h < 8; h++) acc[k][h] = 0ull;
#pragma unroll 2
        for (int cp = 0; cp < 128; cp++) {
            u64 v2 = v2p[(size_t)cp << 8];
            u64 ua = (HAS0 && p == 0) ? utp[(size_t)cp << 8] : usm2[cp][2 * p];
            u64 ub = usm2[cp][2 * p + 1];
            u64 g2 = gbu[cp][0], b2 = gbu[cp][1];
            u64 wv[8];
#pragma unroll
            for (int h = 0; h < 8; h++) wv[h] = whu[cp][h];
#pragma unroll
            for (int k = 0; k < 2; k++) {
                u64 hv = add2_(k == 0 ? ua : ub, v2);
                u64 z = fma2_(hv, r2[2 * p + k], m2[2 * p + k]);
                u64 hn = fma2_(g2, z, b2);
                u64 pr = add2_(hn, hn & ABSM);   // 2*relu(hn); 0.5 folded into wh
#pragma unroll
                for (int h = 0; h < 8; h++) acc[k][h] = fma2_(pr, wv[h], acc[k][h]);
            }
        }
#pragma unroll
        for (int k = 0; k < 2; k++) {
            int il = 2 * p + k;
#pragma unroll
            for (int h = 0; h < 8; h++) {
                float lo, hi; upk2(acc[k][h], lo, hi);
                logits[il][h][j] = lo + hi + sqs[il][h] + skv[h];
            }
        }
    }
}

__global__ void __launch_bounds__(256, 2) k_main(const float* __restrict__ ln_g,
                                                 const float* __restrict__ ln_b,
                                                 float* __restrict__ out) {
    __shared__ u64 usm2[128][4];       // 4 KB  {U[il][2cp], U[il][2cp+1]}
    __shared__ u64 gbu[128][2];        // 2 KB  gamma/beta pairs
    __shared__ u64 whu[128][8];        // 8 KB  head-weight pairs (pre-halved)
    __shared__ float logits[TI][H][S1];// 32 KB (reused as attn)
    __shared__ float sqs[TI][H];
    __shared__ float ceh[H];

    const int t = threadIdx.x, lane = t & 31, w = t >> 5;
    const int b = blockIdx.x / (S1 / TI);
    const int i0 = (blockIdx.x % (S1 / TI)) * TI;
    const bool has0 = (i0 == 0);

    // ---- staging ----
#pragma unroll
    for (int il = 0; il < TI; il++) {
        int gi = i0 + il;
        float uv = (gi >= 1) ? g_U[(b * S + gi - 1) * D + t] : 0.f;
        ((float*)&usm2[t >> 1][il])[t & 1] = uv;
    }
    if (t < 128) {
        gbu[t][0] = pk2(ln_g[2 * t], ln_g[2 * t + 1]);
        gbu[t][1] = pk2(ln_b[2 * t], ln_b[2 * t + 1]);
    }
#pragma unroll
    for (int q = 0; q < 4; q++) {
        int id = t + 256 * q;
        int cp = id & 127, h = id >> 7;
        whu[cp][h] = pk2(g_W2h[h * D + 2 * cp], g_W2h[h * D + 2 * cp + 1]);
    }
    if (t < TI * H) {
        int il = t >> 3, h = t & 7;
        sqs[il][h] = g_sq[(b * H + h) * S1 + i0 + il];
    }
    if (t < H) ceh[t] = g_ce[t];
    __syncthreads();

    // ---- phase 1: per-column edge logits ----
    if (t >= 1) {
        if (has0) edge_cols<true>(b, i0, t, usm2, gbu, whu, logits, sqs, ceh);
        else      edge_cols<false>(b, i0, t, usm2, gbu, whu, logits, sqs, ceh);
    }
    __syncthreads();

    // ---- phase 2: softmax per (il, h) ----
    float* out_attn = out + B * S1 * H * HD;
    for (int rowid = w; rowid < TI * H; rowid += 8) {
        int il = rowid >> 3, h = rowid & 7;
        float vals[8];
        float m = -CUDART_INF_F;
#pragma unroll
        for (int k = 0; k < 8; k++) {
            int j = lane + 32 * k;
            float lv = (j == 0) ? -CUDART_INF_F : logits[il][h][j];
            vals[k] = lv;
            m = fmaxf(m, lv);
        }
#pragma unroll
        for (int o = 16; o > 0; o >>= 1) m = fmaxf(m, __shfl_xor_sync(0xffffffffu, m, o));
        float s = 0.f;
#pragma unroll
        for (int k = 0; k < 8; k++) {
            int j = lane + 32 * k;
            float e = (j == 0) ? 0.f : __expf(vals[k] - m);
            vals[k] = e;
            s += e;
        }
#pragma unroll
        for (int o = 16; o > 0; o >>= 1) s += __shfl_xor_sync(0xffffffffu, s, o);
        float inv = 1.f / s;
        float* arow = out_attn + ((size_t)(b * H + h) * S1 + (i0 + il)) * S1;
#pragma unroll
        for (int k = 0; k < 8; k++) {
            float a = vals[k] * inv;
            arow[lane + 32 * k] = a;
            logits[il][h][lane + 32 * k] = a;
        }
    }
    __syncthreads();

    // ---- phase 3: ctx = attn @ v (warp = head) ----
    {
        const int h = w;
        const float* vb = g_Vmat + ((size_t)b * S1) * D + h * HD + lane;
        float a0 = 0.f, a1 = 0.f, a2 = 0.f, a3 = 0.f;
#pragma unroll 4
        for (int j = 1; j < S1; j++) {
            float vv = vb[(size_t)j * D];
            a0 = fmaf(logits[0][h][j], vv, a0);
            a1 = fmaf(logits[1][h][j], vv, a1);
            a2 = fmaf(logits[2][h][j], vv, a2);
            a3 = fmaf(logits[3][h][j], vv, a3);
        }
        out[(((size_t)b * S1 + i0 + 0) * H + h) * HD + lane] = a0;
        out[(((size_t)b * S1 + i0 + 1) * H + h) * HD + lane] = a1;
        out[(((size_t)b * S1 + i0 + 2) * H + h) * HD + lane] = a2;
        out[(((size_t)b * S1 + i0 + 3) * H + h) * HD + lane] = a3;
    }
}

// ---------------- launch ----------------
extern "C" void kernel_launch(void* const* d_in, const int* in_sizes, int n_in,
                              void* d_out, int out_size) {
    const float* desc = (const float*)d_in[0];
    const float* nve  = (const float*)d_in[1];
    const float* qW = (const float*)d_in[2];
    const float* qb = (const float*)d_in[3];
    const float* kW = (const float*)d_in[4];
    const float* kb = (const float*)d_in[5];
    const float* vW = (const float*)d_in[6];
    const float* vb = (const float*)d_in[7];
    const float* eW1 = (const float*)d_in[8];
    const float* eb1 = (const float*)d_in[9];
    const float* ln_g = (const float*)d_in[10];
    const float* ln_b = (const float*)d_in[11];
    const float* eW2 = (const float*)d_in[12];
    const float* eb2 = (const float*)d_in[13];
    const float* aW = (const float*)d_in[14];
    const float* ab = (const float*)d_in[15];
    float* out = (float*)d_out;

    k_prep<<<25, 256>>>(qW, qb, kW, kb, eW2, eb2, aW, ab);
    k_big<<<224, 256>>>(desc, nve, vW, vb, eW1, eb1);
    k_main<<<B * S1 / TI, 256>>>(ln_g, ln_b, out);
}

// round 4
// speedup vs baseline: 2.0352x; 1.0029x over previous
#include <cuda_runtime.h>
#include <cuda_bf16.h>
#include <math_constants.h>

#define D 256
#define H 8
#define HD 32
#define S 255
#define S1 256
#define B 4
#define TI 4

typedef unsigned long long u64;
typedef ulonglong2 u64x2;

// ---------------- packed f32x2 helpers ----------------
__device__ __forceinline__ u64 pk2(float lo, float hi) {
    u64 r; asm("mov.b64 %0,{%1,%2};" : "=l"(r) : "f"(lo), "f"(hi)); return r;
}
__device__ __forceinline__ void upk2(u64 v, float& lo, float& hi) {
    asm("mov.b64 {%0,%1},%2;" : "=f"(lo), "=f"(hi) : "l"(v));
}
__device__ __forceinline__ u64 fma2_(u64 a, u64 b, u64 c) {
    u64 d; asm("fma.rn.f32x2 %0,%1,%2,%3;" : "=l"(d) : "l"(a), "l"(b), "l"(c)); return d;
}
__device__ __forceinline__ u64 add2_(u64 a, u64 b) {
    u64 d; asm("add.rn.f32x2 %0,%1,%2;" : "=l"(d) : "l"(a), "l"(b)); return d;
}

// ---------------- device scratch ----------------
__device__ float g_U[B * S * D];
__device__ u64   g_UT[B * 128 * S1];
__device__ u64   g_V2T[B * 128 * S1];
__device__ float g_Vmat[B * S1 * D];
__device__ float g_sU[B * S];
__device__ float g_sU2[B * S];
__device__ float g_sV[B * S];
__device__ float g_sV2[B * S];
__device__ float g_sq[B * H * S1];
__device__ float g_sk[B * H * S1];
__device__ float g_aq[H * D];
__device__ float g_ak[H * D];
__device__ float g_W2h[H * D];          // pre-scaled by 0.5 (relu trick)
__device__ float g_bq[H];
__device__ float g_bk[H];
__device__ float g_ce[H];
__device__ float g_vWT[256 * 256];      // vW transposed [in][out]
__device__ float g_eW1T[512 * 256];     // eW1 transposed [in][out]

// ---------------- K1: precompose + weight transposes ----------------
// blocks [0,25): 6144 matrix dots + 24 bias dots
// blocks [25,89): vW 32x32 transpose tiles; [89,217): eW1 tiles
__global__ void __launch_bounds__(256) k_prep(
        const float* __restrict__ qW, const float* __restrict__ qb,
        const float* __restrict__ kW, const float* __restrict__ kb,
        const float* __restrict__ eW2, const float* __restrict__ eb2,
        const float* __restrict__ aW, const float* __restrict__ ab,
        const float* __restrict__ vW, const float* __restrict__ eW1) {
    __shared__ float tsh[32][33];
    int blk = blockIdx.x, t = threadIdx.x;

    if (blk < 25) {
        int id = blk * 256 + t;
        if (id < 3 * H * D) {
            int m = id >> 11;
            int rem = id & 2047;
            int h = rem >> 8, c = rem & 255;
            const float* W = (m == 0) ? qW : (m == 1) ? kW : eW2;
            const float* w = aW + m * HD;
            float s = 0.f;
#pragma unroll
            for (int d = 0; d < HD; d++)
                s = fmaf(__ldg(&w[d]), W[(h * HD + d) * D + c], s);
            if (m == 0) g_aq[h * D + c] = s;
            else if (m == 1) g_ak[h * D + c] = s;
            else g_W2h[h * D + c] = 0.5f * s;
        } else if (id < 3 * H * D + 3 * H) {
            int r = id - 3 * H * D;
            int m = r >> 3, h = r & 7;
            const float* bb = (m == 0) ? qb : (m == 1) ? kb : eb2;
            const float* w = aW + m * HD;
            float s = (m == 0) ? ab[0] : 0.f;
#pragma unroll
            for (int d = 0; d < HD; d++)
                s = fmaf(w[d], bb[h * HD + d], s);
            if (m == 0) g_bq[h] = s;
            else if (m == 1) g_bk[h] = s;
            else g_ce[h] = s;
        }
        return;
    }

    // ---- transpose tiles ----
    int tt = blk - 25;
    const float* Wsrc; float* Wdst; int srcw, ot, it;
    if (tt < 64) { Wsrc = vW;  Wdst = g_vWT;  srcw = 256; ot = tt >> 3; it = tt & 7; }
    else { tt -= 64; Wsrc = eW1; Wdst = g_eW1T; srcw = 512; ot = tt >> 4; it = tt & 15; }
    int r = t >> 5, c = t & 31;
#pragma unroll
    for (int k = 0; k < 4; k++)
        tsh[r + 8 * k][c] = Wsrc[(ot * 32 + r + 8 * k) * srcw + it * 32 + c];
    __syncthreads();
#pragma unroll
    for (int k = 0; k < 4; k++)
        Wdst[(it * 32 + r + 8 * k) * 256 + ot * 32 + c] = tsh[c][r + 8 * k];
}

// ---------------- K2: fused GEMMs (coalesced WT) + transposes + row stats + sq/sk ----------------
// blocks [0,64): Vmat; [64,128): U; [128,192): V2T; [192,224): sqsk
__global__ void __launch_bounds__(256) k_big(const float* __restrict__ desc,
                                             const float* __restrict__ nve,
                                             const float* __restrict__ vb,
                                             const float* __restrict__ eb1) {
    __shared__ __align__(16) u64 xsp[D][8];   // [channel][rowpair]
    __shared__ float red[8][4][2];            // [warp][row-in-group][s,s2]
    int blk = blockIdx.x;
    int t = threadIdx.x;

    if (blk >= 192) {  // ---- sqsk job ----
        int task = (blk - 192) * 256 + t;
        int row = task >> 3, h = task & 7;
        const float* x = nve + row * D;
        const float* aq = g_aq + h * D;
        const float* ak = g_ak + h * D;
        float sq = g_bq[h], sk = g_bk[h];
#pragma unroll 8
        for (int in = 0; in < D; in++) {
            float xv = x[in];
            sq += xv * aq[in];
            sk += xv * ak[in];
        }
        int b = row >> 8, i = row & 255;
        g_sq[(b * H + h) * S1 + i] = sq;
        g_sk[(b * H + h) * S1 + i] = sk;
        return;
    }

    int job = blk >> 6;
    int r0 = (blk & 63) * 16;
    const float* X; const float* WT; const float* bias; int nrows;
    if (job == 0) { X = nve;  WT = g_vWT;              bias = vb;      nrows = B * S1; }
    else if (job == 1) { X = desc; WT = g_eW1T;        bias = nullptr; nrows = B * S; }
    else { X = desc; WT = g_eW1T + 256 * 256;          bias = eb1;     nrows = B * S; }

    // stage X rows (row-pair packed); t = channel
#pragma unroll
    for (int r = 0; r < 16; r++) {
        int rr = r0 + r;
        float xv = (rr < nrows) ? X[rr * D + t] : 0.f;
        ((float*)&xsp[t][r >> 1])[r & 1] = xv;
    }
    __syncthreads();

    // 4row x 4out register blocking
    const int rg = t >> 6;       // 0..3  row group (rows rg*4..+3)
    const int og = t & 63;       // 0..63 out group (outs og*4..+3)
    u64 acc[2][4];
#pragma unroll
    for (int k = 0; k < 2; k++)
#pragma unroll
        for (int o = 0; o < 4; o++) acc[k][o] = 0ull;

#pragma unroll 4
    for (int c = 0; c < D; c++) {
        u64x2 xv = *(const u64x2*)&xsp[c][2 * rg];
        float4 wv = ((const float4*)(WT + c * 256))[og];
        u64 w0 = pk2(wv.x, wv.x), w1 = pk2(wv.y, wv.y);
        u64 w2 = pk2(wv.z, wv.z), w3 = pk2(wv.w, wv.w);
        acc[0][0] = fma2_(xv.x, w0, acc[0][0]); acc[1][0] = fma2_(xv.y, w0, acc[1][0]);
        acc[0][1] = fma2_(xv.x, w1, acc[0][1]); acc[1][1] = fma2_(xv.y, w1, acc[1][1]);
        acc[0][2] = fma2_(xv.x, w2, acc[0][2]); acc[1][2] = fma2_(xv.y, w2, acc[1][2]);
        acc[0][3] = fma2_(xv.x, w3, acc[0][3]); acc[1][3] = fma2_(xv.y, w3, acc[1][3]);
    }

    float vals[4][4];   // [row][out]
#pragma unroll
    for (int k = 0; k < 2; k++)
#pragma unroll
        for (int o = 0; o < 4; o++)
            upk2(acc[k][o], vals[2 * k][o], vals[2 * k + 1][o]);
    if (bias) {
#pragma unroll
        for (int o = 0; o < 4; o++) {
            float bv = bias[og * 4 + o];
#pragma unroll
            for (int r = 0; r < 4; r++) vals[r][o] += bv;
        }
    }

    if (job == 0) {
#pragma unroll
        for (int r = 0; r < 4; r++) {
            int rr = r0 + rg * 4 + r;
            float4 o4 = make_float4(vals[r][0], vals[r][1], vals[r][2], vals[r][3]);
            *(float4*)&g_Vmat[rr * D + og * 4] = o4;
        }
        return;
    }

    // jobs 1/2: transposed (+ row-major for job 1) stores
#pragma unroll
    for (int r = 0; r < 4; r++) {
        int rr = r0 + rg * 4 + r;
        if (rr < nrows) {
            int bb = rr / S, jm = rr % S, j = jm + 1;
            int cp0 = og * 2;
            u64 lo = pk2(vals[r][0], vals[r][1]);
            u64 hi = pk2(vals[r][2], vals[r][3]);
            if (job == 1) {
                float4 o4 = make_float4(vals[r][0], vals[r][1], vals[r][2], vals[r][3]);
                *(float4*)&g_U[rr * D + og * 4] = o4;
                g_UT[(size_t)(bb * 128 + cp0) * S1 + j] = lo;
                g_UT[(size_t)(bb * 128 + cp0 + 1) * S1 + j] = hi;
            } else {
                g_V2T[(size_t)(bb * 128 + cp0) * S1 + j] = lo;
                g_V2T[(size_t)(bb * 128 + cp0 + 1) * S1 + j] = hi;
            }
        }
    }

    // row sums / sumsq: thread partials over its 4 outs, reduce over og (2 warps)
    int lane = t & 31, w = t >> 5;
    float ps[4], ps2[4];
#pragma unroll
    for (int r = 0; r < 4; r++) {
        float s = vals[r][0] + vals[r][1] + vals[r][2] + vals[r][3];
        float s2 = vals[r][0] * vals[r][0] + vals[r][1] * vals[r][1]
                 + vals[r][2] * vals[r][2] + vals[r][3] * vals[r][3];
#pragma unroll
        for (int o = 16; o > 0; o >>= 1) {
            s += __shfl_xor_sync(0xffffffffu, s, o);
            s2 += __shfl_xor_sync(0xffffffffu, s2, o);
        }
        ps[r] = s; ps2[r] = s2;
    }
    if (lane == 0) {
#pragma unroll
        for (int r = 0; r < 4; r++) { red[w][r][0] = ps[r]; red[w][r][1] = ps2[r]; }
    }
    __syncthreads();
    if (t < 16) {
        int rr = r0 + t;                 // rg = t>>2, r = t&3
        if (rr < nrows) {
            int rgq = t >> 2, rq = t & 3;
            float s = red[2 * rgq][rq][0] + red[2 * rgq + 1][rq][0];
            float s2 = red[2 * rgq][rq][1] + red[2 * rgq + 1][rq][1];
            if (job == 1) { g_sU[rr] = s; g_sU2[rr] = s2; }
            else { g_sV[rr] = s; g_sV2[rr] = s2; }
        }
    }
}

// ---------------- K3 main ----------------
template <bool HAS0>
__device__ __forceinline__ void edge_cols(int b, int i0, int j,
                                          u64 (&usm2)[128][4], u64 (&gbu)[128][2],
                                          u64 (&whu)[128][8], float (&logits)[TI][H][S1],
                                          float (&sqs)[TI][H], float (&ceh)[H]) {
    const u64* v2p = g_V2T + (size_t)b * 128 * S1 + j;
    const u64* utp = g_UT + (size_t)b * 128 * S1 + j;

    // ---- pass 1: cross dots for variance ----
    u64 d2[4] = {0ull, 0ull, 0ull, 0ull};
#pragma unroll 4
    for (int cp = 0; cp < 128; cp++) {
        u64 v2 = v2p[(size_t)cp << 8];
        u64x2 uA = *(const u64x2*)&usm2[cp][0];
        u64x2 uB = *(const u64x2*)&usm2[cp][2];
        u64 u0 = HAS0 ? utp[(size_t)cp << 8] : uA.x;
        d2[0] = fma2_(u0, v2, d2[0]);
        d2[1] = fma2_(uA.y, v2, d2[1]);
        d2[2] = fma2_(uB.x, v2, d2[2]);
        d2[3] = fma2_(uB.y, v2, d2[3]);
    }

    float sv = g_sV[b * S + j - 1], sv2 = g_sV2[b * S + j - 1];
    u64 r2[4], m2[4];
#pragma unroll
    for (int il = 0; il < 4; il++) {
        int gi = i0 + il;
        float su, su2;
        if (HAS0 && il == 0) { su = g_sU[b * S + j - 1]; su2 = g_sU2[b * S + j - 1]; }
        else { su = g_sU[b * S + gi - 1]; su2 = g_sU2[b * S + gi - 1]; }
        float dlo, dhi; upk2(d2[il], dlo, dhi);
        float dot = dlo + dhi;
        float mean = (su + sv) * (1.f / D);
        float msum = su2 + sv2 + 2.f * dot;
        float var = msum * (1.f / D) - mean * mean;
        float rstd = rsqrtf(var + 1e-5f);
        r2[il] = pk2(rstd, rstd);
        float nm = -mean * rstd;
        m2[il] = pk2(nm, nm);
    }

    float skv[H];
#pragma unroll
    for (int h = 0; h < H; h++) skv[h] = g_sk[(b * H + h) * S1 + j] + ceh[h];

    const u64 ABSM = 0x7FFFFFFF7FFFFFFFull;
#pragma unroll
    for (int p = 0; p < 2; p++) {
        u64 acc[2][8];
#pragma unroll
        for (int k = 0; k < 2; k++)
#pragma unroll
            for (int h = 0; h < 8; h++) acc[k][h] = 0ull;
#pragma unroll 2
        for (int cp = 0; cp < 128; cp++) {
            u64 v2 = v2p[(size_t)cp << 8];
            u64x2 us = *(const u64x2*)&usm2[cp][2 * p];
            u64 ua = (HAS0 && p == 0) ? utp[(size_t)cp << 8] : us.x;
            u64 ub = us.y;
            u64x2 gb = *(const u64x2*)&gbu[cp][0];
            u64x2 w01 = *(const u64x2*)&whu[cp][0];
            u64x2 w23 = *(const u64x2*)&whu[cp][2];
            u64x2 w45 = *(const u64x2*)&whu[cp][4];
            u64x2 w67 = *(const u64x2*)&whu[cp][6];
#pragma unroll
            for (int k = 0; k < 2; k++) {
                u64 hv = add2_(k == 0 ? ua : ub, v2);
                u64 z = fma2_(hv, r2[2 * p + k], m2[2 * p + k]);
                u64 hn = fma2_(gb.x, z, gb.y);
                u64 pr = add2_(hn, hn & ABSM);   // 2*relu(hn); 0.5 folded into wh
                acc[k][0] = fma2_(pr, w01.x, acc[k][0]);
                acc[k][1] = fma2_(pr, w01.y, acc[k][1]);
                acc[k][2] = fma2_(pr, w23.x, acc[k][2]);
                acc[k][3] = fma2_(pr, w23.y, acc[k][3]);
                acc[k][4] = fma2_(pr, w45.x, acc[k][4]);
                acc[k][5] = fma2_(pr, w45.y, acc[k][5]);
                acc[k][6] = fma2_(pr, w67.x, acc[k][6]);
                acc[k][7] = fma2_(pr, w67.y, acc[k][7]);
            }
        }
#pragma unroll
        for (int k = 0; k < 2; k++) {
            int il = 2 * p + k;
#pragma unroll
            for (int h = 0; h < 8; h++) {
                float lo, hi; upk2(acc[k][h], lo, hi);
                logits[il][h][j] = lo + hi + sqs[il][h] + skv[h];
            }
        }
    }
}

__global__ void __launch_bounds__(256, 2) k_main(const float* __restrict__ ln_g,
                                                 const float* __restrict__ ln_b,
                                                 float* __restrict__ out) {
    __shared__ __align__(16) u64 usm2[128][4];
    __shared__ __align__(16) u64 gbu[128][2];
    __shared__ __align__(16) u64 whu[128][8];
    __shared__ float logits[TI][H][S1];
    __shared__ float sqs[TI][H];
    __shared__ float ceh[H];

    const int t = threadIdx.x, lane = t & 31, w = t >> 5;
    const int b = blockIdx.x / (S1 / TI);
    const int i0 = (blockIdx.x % (S1 / TI)) * TI;
    const bool has0 = (i0 == 0);

#pragma unroll
    for (int il = 0; il < TI; il++) {
        int gi = i0 + il;
        float uv = (gi >= 1) ? g_U[(b * S + gi - 1) * D + t] : 0.f;
        ((float*)&usm2[t >> 1][il])[t & 1] = uv;
    }
    if (t < 128) {
        gbu[t][0] = pk2(ln_g[2 * t], ln_g[2 * t + 1]);
        gbu[t][1] = pk2(ln_b[2 * t], ln_b[2 * t + 1]);
    }
#pragma unroll
    for (int q = 0; q < 4; q++) {
        int id = t + 256 * q;
        int cp = id & 127, h = id >> 7;
        whu[cp][h] = pk2(g_W2h[h * D + 2 * cp], g_W2h[h * D + 2 * cp + 1]);
    }
    if (t < TI * H) {
        int il = t >> 3, h = t & 7;
        sqs[il][h] = g_sq[(b * H + h) * S1 + i0 + il];
    }
    if (t < H) ceh[t] = g_ce[t];
    __syncthreads();

    if (t >= 1) {
        if (has0) edge_cols<true>(b, i0, t, usm2, gbu, whu, logits, sqs, ceh);
        else      edge_cols<false>(b, i0, t, usm2, gbu, whu, logits, sqs, ceh);
    }
    __syncthreads();

    float* out_attn = out + B * S1 * H * HD;
    for (int rowid = w; rowid < TI * H; rowid += 8) {
        int il = rowid >> 3, h = rowid & 7;
        float vals[8];
        float m = -CUDART_INF_F;
#pragma unroll
        for (int k = 0; k < 8; k++) {
            int j = lane + 32 * k;
            float lv = (j == 0) ? -CUDART_INF_F : logits[il][h][j];
            vals[k] = lv;
            m = fmaxf(m, lv);
        }
#pragma unroll
        for (int o = 16; o > 0; o >>= 1) m = fmaxf(m, __shfl_xor_sync(0xffffffffu, m, o));
        float s = 0.f;
#pragma unroll
        for (int k = 0; k < 8; k++) {
            int j = lane + 32 * k;
            float e = (j == 0) ? 0.f : __expf(vals[k] - m);
            vals[k] = e;
            s += e;
        }
#pragma unroll
        for (int o = 16; o > 0; o >>= 1) s += __shfl_xor_sync(0xffffffffu, s, o);
        float inv = 1.f / s;
        float* arow = out_attn + ((size_t)(b * H + h) * S1 + (i0 + il)) * S1;
#pragma unroll
        for (int k = 0; k < 8; k++) {
            float a = vals[k] * inv;
            arow[lane + 32 * k] = a;
            logits[il][h][lane + 32 * k] = a;
        }
    }
    __syncthreads();

    {
        const int h = w;
        const float* vb = g_Vmat + ((size_t)b * S1) * D + h * HD + lane;
        float a0 = 0.f, a1 = 0.f, a2 = 0.f, a3 = 0.f;
#pragma unroll 4
        for (int j = 1; j < S1; j++) {
            float vv = vb[(size_t)j * D];
            a0 = fmaf(logits[0][h][j], vv, a0);
            a1 = fmaf(logits[1][h][j], vv, a1);
            a2 = fmaf(logits[2][h][j], vv, a2);
            a3 = fmaf(logits[3][h][j], vv, a3);
        }
        out[(((size_t)b * S1 + i0 + 0) * H + h) * HD + lane] = a0;
        out[(((size_t)b * S1 + i0 + 1) * H + h) * HD + lane] = a1;
        out[(((size_t)b * S1 + i0 + 2) * H + h) * HD + lane] = a2;
        out[(((size_t)b * S1 + i0 + 3) * H + h) * HD + lane] = a3;
    }
}

// ---------------- launch ----------------
extern "C" void kernel_launch(void* const* d_in, const int* in_sizes, int n_in,
                              void* d_out, int out_size) {
    const float* desc = (const float*)d_in[0];
    const float* nve  = (const float*)d_in[1];
    const float* qW = (const float*)d_in[2];
    const float* qb = (const float*)d_in[3];
    const float* kW = (const float*)d_in[4];
    const float* kb = (const float*)d_in[5];
    const float* vW = (const float*)d_in[6];
    const float* vb = (const float*)d_in[7];
    const float* eW1 = (const float*)d_in[8];
    const float* eb1 = (const float*)d_in[9];
    const float* ln_g = (const float*)d_in[10];
    const float* ln_b = (const float*)d_in[11];
    const float* eW2 = (const float*)d_in[12];
    const float* eb2 = (const float*)d_in[13];
    const float* aW = (const float*)d_in[14];
    const float* ab = (const float*)d_in[15];
    float* out = (float*)d_out;

    k_prep<<<217, 256>>>(qW, qb, kW, kb, eW2, eb2, aW, ab, vW, eW1);
    k_big<<<224, 256>>>(desc, nve, vb, eb1);
    k_main<<<B * S1 / TI, 256>>>(ln_g, ln_b, out);
}